// round 10
// baseline (speedup 1.0000x reference)
#include <cuda_runtime.h>
#include <cuda_fp16.h>

#define NN 100000
#define NE 1200000
#define ELLW 64      // max degree capacity (Poisson(12): P(d>=64) ~ 1e-30)
#define APITCH 36    // uint (half2) pitch per smem row: 144 B, LDSM conflict-free

// Scratch (device globals — no allocation allowed). Row NN of HA/HB is all-zero.
__device__ unsigned HA[(size_t)(NN + 1) * 32];
__device__ unsigned HB[(size_t)(NN + 1) * 32];
__device__ unsigned H3[(size_t)NN * 8];    // layer-3 g, fp16x2 (16 feats)
__device__ int   ESRC[(size_t)NN * ELLW];  // ELL: src ids grouped by dst
__device__ int   CUR[NN];                  // slot counter == degree after place
__device__ float DINV[NN];
__device__ float GSTATS[32];               // [0..4] x-stats, [8..23] embedding sums

// ---------------------------------------------------------------------------
__global__ void k_place(const int* __restrict__ ei) {
    int e = blockIdx.x * blockDim.x + threadIdx.x;
    if (e < NE) {
        int src = ei[e], dst = ei[NE + e];
        int c = atomicAdd(&CUR[dst], 1);
        if (c < ELLW) ESRC[dst * ELLW + c] = src;
    }
}

// Layer 1 + dinv + x-stats. Warp per node, lane = feat pair. Also zeroes row NN.
__global__ void k_xw1(const float* __restrict__ x, const float* __restrict__ W1) {
    __shared__ float2 W1s[160];
    __shared__ float bins[5];
    int t = threadIdx.x;
    if (t < 160) W1s[t] = ((const float2*)W1)[t];
    if (t < 5) bins[t] = 0.0f;
    if (blockIdx.x == 0 && t < 32) { HA[NN * 32 + t] = 0; HB[NN * 32 + t] = 0; }
    __syncthreads();
    int lane = t & 31, w = t >> 5;
    int node = blockIdx.x * 8 + w;
    float di = rsqrtf((float)CUR[node] + 1.0f);
    float xv = (lane < 5) ? x[node * 5 + lane] : 0.0f;
    float2 s = make_float2(0.f, 0.f);
    float xs[5];
    #pragma unroll
    for (int i = 0; i < 5; i++) {
        float xi = __shfl_sync(0xffffffffu, xv, i);
        xs[i] = xi;
        float2 wv = W1s[i * 32 + lane];
        s.x += xi * wv.x; s.y += xi * wv.y;
    }
    if (lane == 0) {
        DINV[node] = di;
        atomicAdd(&bins[0], xs[2]);
        atomicAdd(&bins[1], xs[3]);
        atomicAdd(&bins[2], xs[4]);
        atomicAdd(&bins[3], xs[0] * xs[2]);
        atomicAdd(&bins[4], xs[1] * xs[2]);
    }
    __half2 o = __floats2half2_rn(s.x * di, s.y * di);
    HA[node * 32 + lane] = *(unsigned*)&o;
    __syncthreads();
    if (t < 5) atomicAdd(&GSTATS[t], bins[t]);
}

__device__ __forceinline__ unsigned sm_u32(const void* p) {
    return (unsigned)__cvta_generic_to_shared(p);
}

__device__ __forceinline__ void hacc4(__half2& a0, __half2& a1, __half2& a2, __half2& a3,
                                      const uint4& v) {
    a0 = __hadd2(a0, ((const __half2*)&v)[0]);
    a1 = __hadd2(a1, ((const __half2*)&v)[1]);
    a2 = __hadd2(a2, ((const __half2*)&v)[2]);
    a3 = __hadd2(a3, ((const __half2*)&v)[3]);
}

// Warp gathers 4 consecutive nodes (8 lanes/node, uint4/lane = 8 feats).
// 8 indices broadcast up front; loads in two half-batches of 4 to bound regs.
__device__ __forceinline__ void gather4_to_tile(
    const uint4* __restrict__ H4,       // (NN+1) x 8 uint4, row NN zero
    const float2* __restrict__ bs2,     // bias, 32 float2 (smem)
    int node0, int lane,
    unsigned* Arow,                     // &Aw[r * APITCH]
    float* dis)                         // &Dis[w][r]
{
    int g = lane >> 3, u = lane & 7;
    int node = node0 + g;
    int d = CUR[node]; if (d > ELLW) d = ELLW;
    float di = DINV[node];
    uint4 v = H4[node * 8 + u];
    __half2 a0 = ((__half2*)&v)[0], a1 = ((__half2*)&v)[1];
    __half2 a2 = ((__half2*)&v)[2], a3 = ((__half2*)&v)[3];
    int dmax = d;
    dmax = max(dmax, __shfl_xor_sync(0xffffffffu, dmax, 8));
    dmax = max(dmax, __shfl_xor_sync(0xffffffffu, dmax, 16));
    const int* row = &ESRC[node * ELLW];
    for (int base = 0; base < dmax; base += 8) {
        int idxv = (base + u < d) ? row[base + u] : NN;   // NN = zero row
        int s0 = __shfl_sync(0xffffffffu, idxv, 0, 8);
        int s1 = __shfl_sync(0xffffffffu, idxv, 1, 8);
        int s2 = __shfl_sync(0xffffffffu, idxv, 2, 8);
        int s3 = __shfl_sync(0xffffffffu, idxv, 3, 8);
        int s4 = __shfl_sync(0xffffffffu, idxv, 4, 8);
        int s5 = __shfl_sync(0xffffffffu, idxv, 5, 8);
        int s6 = __shfl_sync(0xffffffffu, idxv, 6, 8);
        int s7 = __shfl_sync(0xffffffffu, idxv, 7, 8);
        {
            uint4 n0 = H4[s0 * 8 + u];
            uint4 n1 = H4[s1 * 8 + u];
            uint4 n2 = H4[s2 * 8 + u];
            uint4 n3 = H4[s3 * 8 + u];
            hacc4(a0, a1, a2, a3, n0);
            hacc4(a0, a1, a2, a3, n1);
            hacc4(a0, a1, a2, a3, n2);
            hacc4(a0, a1, a2, a3, n3);
        }
        {
            uint4 n4 = H4[s4 * 8 + u];
            uint4 n5 = H4[s5 * 8 + u];
            uint4 n6 = H4[s6 * 8 + u];
            uint4 n7 = H4[s7 * 8 + u];
            hacc4(a0, a1, a2, a3, n4);
            hacc4(a0, a1, a2, a3, n5);
            hacc4(a0, a1, a2, a3, n6);
            hacc4(a0, a1, a2, a3, n7);
        }
    }
    uint4 o;
    {
        float2 b = bs2[u * 4 + 0], f = __half22float2(a0);
        __half2 h = __floats2half2_rn(fmaxf(di * f.x + b.x, 0.f), fmaxf(di * f.y + b.y, 0.f));
        o.x = *(unsigned*)&h;
    }
    {
        float2 b = bs2[u * 4 + 1], f = __half22float2(a1);
        __half2 h = __floats2half2_rn(fmaxf(di * f.x + b.x, 0.f), fmaxf(di * f.y + b.y, 0.f));
        o.y = *(unsigned*)&h;
    }
    {
        float2 b = bs2[u * 4 + 2], f = __half22float2(a2);
        __half2 h = __floats2half2_rn(fmaxf(di * f.x + b.x, 0.f), fmaxf(di * f.y + b.y, 0.f));
        o.z = *(unsigned*)&h;
    }
    {
        float2 b = bs2[u * 4 + 3], f = __half22float2(a3);
        __half2 h = __floats2half2_rn(fmaxf(di * f.x + b.x, 0.f), fmaxf(di * f.y + b.y, 0.f));
        o.w = *(unsigned*)&h;
    }
    *(uint4*)&Arow[g * APITCH + u * 4] = o;
    if (u == 0) dis[g] = di;
}

// gl2: gather HA (16 nodes/warp), HMMA 16x64x64, -> HB
__global__ void __launch_bounds__(256, 5) k_gl2(const float* __restrict__ W2,
                                                const float* __restrict__ b1) {
    __shared__ unsigned As[8][16 * APITCH];
    __shared__ unsigned W2h[64 * APITCH];
    __shared__ float    Dis[8][16];
    __shared__ float2   b1s[32];
    int t = threadIdx.x;
    for (int idx = t; idx < 2048; idx += 256) {
        int k = idx >> 5, np = idx & 31;
        __half2 wv = __floats2half2_rn(W2[k * 64 + 2 * np], W2[k * 64 + 2 * np + 1]);
        W2h[k * APITCH + np] = *(unsigned*)&wv;
    }
    if (t < 32) b1s[t] = ((const float2*)b1)[t];
    __syncthreads();
    int lane = t & 31, w = t >> 5;
    int gw = blockIdx.x * 8 + w;
    if (gw >= NN / 16) return;
    int gbase = gw * 16;
    unsigned* Aw = As[w];

    #pragma unroll
    for (int r = 0; r < 16; r += 4)
        gather4_to_tile((const uint4*)HA, b1s, gbase + r, lane, &Aw[r * APITCH], &Dis[w][r]);
    __syncwarp();

    unsigned a0[4], a1[4], a2[4], a3[4];
    {
        int tt = lane >> 3, i = lane & 7;
        int ar = i + ((tt & 1) << 3);
        #pragma unroll
        for (int ks = 0; ks < 4; ks++) {
            unsigned addr = sm_u32(&Aw[ar * APITCH + ks * 8 + ((tt >> 1) << 2)]);
            asm volatile("ldmatrix.sync.aligned.m8n8.x4.shared.b16 {%0,%1,%2,%3}, [%4];"
                         : "=r"(a0[ks]), "=r"(a1[ks]), "=r"(a2[ks]), "=r"(a3[ks])
                         : "r"(addr));
        }
    }
    float di0 = Dis[w][lane >> 2];
    float di1 = Dis[w][(lane >> 2) + 8];
    int n0 = gbase + (lane >> 2);
    int n1 = n0 + 8;
    int bl = lane & 15;
    int bi = bl & 7, bh = (bl >> 3) & 1;

    #pragma unroll
    for (int nt = 0; nt < 8; nt++) {
        float d0 = 0.f, d1 = 0.f, d2 = 0.f, d3 = 0.f;
        #pragma unroll
        for (int ks = 0; ks < 4; ks++) {
            unsigned b0, b1r;
            unsigned baddr = sm_u32(&W2h[(ks * 16 + bh * 8 + bi) * APITCH + nt * 4]);
            asm volatile("ldmatrix.sync.aligned.m8n8.x2.trans.shared.b16 {%0,%1}, [%2];"
                         : "=r"(b0), "=r"(b1r) : "r"(baddr));
            asm volatile("mma.sync.aligned.m16n8k16.row.col.f32.f16.f16.f32 "
                         "{%0,%1,%2,%3}, {%4,%5,%6,%7}, {%8,%9}, {%0,%1,%2,%3};"
                         : "+f"(d0), "+f"(d1), "+f"(d2), "+f"(d3)
                         : "r"(a0[ks]), "r"(a1[ks]), "r"(a2[ks]), "r"(a3[ks]),
                           "r"(b0), "r"(b1r));
        }
        __half2 h0 = __floats2half2_rn(d0 * di0, d1 * di0);
        __half2 h1 = __floats2half2_rn(d2 * di1, d3 * di1);
        HB[n0 * 32 + nt * 4 + (lane & 3)] = *(unsigned*)&h0;
        HB[n1 * 32 + nt * 4 + (lane & 3)] = *(unsigned*)&h1;
    }
}

// gl3: gather HB (16 nodes/warp), HMMA 16x16x64, -> H3 + self term into GSTATS
__global__ void __launch_bounds__(256, 5) k_gl3(const float* __restrict__ W3,
                                                const float* __restrict__ b2) {
    __shared__ unsigned As[8][16 * APITCH];
    __shared__ unsigned W3h[64 * APITCH];
    __shared__ float    Dis[8][16];
    __shared__ float2   b2s[32];
    __shared__ float    sbin[16];
    int t = threadIdx.x;
    for (int idx = t; idx < 512; idx += 256) {
        int k = idx >> 3, p = idx & 7;
        __half2 wv = __floats2half2_rn(W3[k * 16 + 2 * p], W3[k * 16 + 2 * p + 1]);
        W3h[k * APITCH + p] = *(unsigned*)&wv;
    }
    if (t < 32) b2s[t] = ((const float2*)b2)[t];
    if (t < 16) sbin[t] = 0.0f;
    __syncthreads();
    int lane = t & 31, w = t >> 5;
    int gw = blockIdx.x * 8 + w;
    if (gw < NN / 16) {
        int gbase = gw * 16;
        unsigned* Aw = As[w];

        #pragma unroll
        for (int r = 0; r < 16; r += 4)
            gather4_to_tile((const uint4*)HB, b2s, gbase + r, lane, &Aw[r * APITCH], &Dis[w][r]);
        __syncwarp();

        unsigned a0[4], a1[4], a2[4], a3[4];
        {
            int tt = lane >> 3, i = lane & 7;
            int ar = i + ((tt & 1) << 3);
            #pragma unroll
            for (int ks = 0; ks < 4; ks++) {
                unsigned addr = sm_u32(&Aw[ar * APITCH + ks * 8 + ((tt >> 1) << 2)]);
                asm volatile("ldmatrix.sync.aligned.m8n8.x4.shared.b16 {%0,%1,%2,%3}, [%4];"
                             : "=r"(a0[ks]), "=r"(a1[ks]), "=r"(a2[ks]), "=r"(a3[ks])
                             : "r"(addr));
            }
        }
        float di0 = Dis[w][lane >> 2];
        float di1 = Dis[w][(lane >> 2) + 8];
        int n0 = gbase + (lane >> 2);
        int n1 = n0 + 8;
        int bl = lane & 15;
        int bi = bl & 7, bh = (bl >> 3) & 1;
        float s0 = 0.f, s1 = 0.f, s2 = 0.f, s3 = 0.f;

        #pragma unroll
        for (int nt = 0; nt < 2; nt++) {
            float d0 = 0.f, d1 = 0.f, d2 = 0.f, d3 = 0.f;
            #pragma unroll
            for (int ks = 0; ks < 4; ks++) {
                unsigned b0, b1r;
                unsigned baddr = sm_u32(&W3h[(ks * 16 + bh * 8 + bi) * APITCH + nt * 4]);
                asm volatile("ldmatrix.sync.aligned.m8n8.x2.trans.shared.b16 {%0,%1}, [%2];"
                             : "=r"(b0), "=r"(b1r) : "r"(baddr));
                asm volatile("mma.sync.aligned.m16n8k16.row.col.f32.f16.f16.f32 "
                             "{%0,%1,%2,%3}, {%4,%5,%6,%7}, {%8,%9}, {%0,%1,%2,%3};"
                             : "+f"(d0), "+f"(d1), "+f"(d2), "+f"(d3)
                             : "r"(a0[ks]), "r"(a1[ks]), "r"(a2[ks]), "r"(a3[ks]),
                               "r"(b0), "r"(b1r));
            }
            float g0 = d0 * di0, g1 = d1 * di0, g2 = d2 * di1, g3v = d3 * di1;
            __half2 h0 = __floats2half2_rn(g0, g1);
            __half2 h1 = __floats2half2_rn(g2, g3v);
            H3[n0 * 8 + nt * 4 + (lane & 3)] = *(unsigned*)&h0;
            H3[n1 * 8 + nt * 4 + (lane & 3)] = *(unsigned*)&h1;
            if (nt == 0) { s0 = g0 * di0 + g2 * di1; s1 = g1 * di0 + g3v * di1; }
            else         { s2 = g0 * di0 + g2 * di1; s3 = g1 * di0 + g3v * di1; }
        }
        int j0 = 2 * (lane & 3);
        atomicAdd(&sbin[j0],     s0);
        atomicAdd(&sbin[j0 + 1], s1);
        atomicAdd(&sbin[8 + j0],     s2);
        atomicAdd(&sbin[8 + j0 + 1], s3);
    }
    __syncthreads();
    if (t < 16) atomicAdd(&GSTATS[8 + t], sbin[t]);
}

// Edge-parallel final reduce: sum_e g3[src] * dinv[dst]. 8 lanes/edge, 4 edges/warp.
__global__ void k_gr(const int* __restrict__ ei) {
    __shared__ float sbin[16];
    int t = threadIdx.x;
    if (t < 16) sbin[t] = 0.0f;
    __syncthreads();
    int u = t & 7;
    int slot = (t >> 3) & 3;
    int gw = blockIdx.x * 8 + (t >> 5);
    int eb = gw * 64 + slot;
    float2 acc = make_float2(0.f, 0.f);
    #pragma unroll 4
    for (int it = 0; it < 16; it++) {
        int e = eb + it * 4;
        if (e < NE) {
            int src = ei[e], dst = ei[NE + e];
            unsigned v = H3[src * 8 + u];
            float2 f = __half22float2(*(__half2*)&v);
            float dd = DINV[dst];
            acc.x += f.x * dd; acc.y += f.y * dd;
        }
    }
    atomicAdd(&sbin[2 * u], acc.x);
    atomicAdd(&sbin[2 * u + 1], acc.y);
    __syncthreads();
    if (t < 16) atomicAdd(&GSTATS[8 + t], sbin[t]);
}

__device__ __forceinline__ float softplusf(float v) {
    return fmaxf(v, 0.0f) + log1pf(expf(-fabsf(v)));
}

// Final MLP head, single block of 64 threads
__global__ void k_mlp(const float* __restrict__ T, const float* __restrict__ Tm,
                      const float* __restrict__ b3,
                      const float* __restrict__ P1, const float* __restrict__ pb1,
                      const float* __restrict__ P2, const float* __restrict__ pb2,
                      const float* __restrict__ P3, const float* __restrict__ pb3,
                      float* __restrict__ out) {
    __shared__ float emb[24], h1[64], h2[32], val[4];
    int tid = threadIdx.x;
    if (tid < 16) emb[tid] = GSTATS[8 + tid] * (1.0f / NN) + b3[tid];
    if (tid == 0) {
        float ncomp = GSTATS[0], nAND = GSTATS[1], nOR = GSTATS[2];
        float slam = GSTATS[3], smu = GSTATS[4];
        float Tn = T[0] / Tm[0];
        float safe = fmaxf(ncomp, 1.0f);
        bool has = ncomp > 0.0f;
        emb[16] = ncomp; emb[17] = nAND; emb[18] = nOR; emb[19] = nAND + nOR;
        emb[20] = has ? slam / safe : 0.0f;
        emb[21] = has ? smu / safe : 0.0f;
        emb[22] = Tn * 50.0f;
        emb[23] = (1.0f / (1.0f + Tn)) * 50.0f;
    }
    __syncthreads();
    {
        float s = pb1[tid];
        #pragma unroll
        for (int k = 0; k < 24; k++) s += emb[k] * P1[k * 64 + tid];
        h1[tid] = fmaxf(s, 0.0f);
    }
    __syncthreads();
    if (tid < 32) {
        float s = pb2[tid];
        #pragma unroll
        for (int k = 0; k < 64; k++) s += h1[k] * P2[k * 32 + tid];
        h2[tid] = fmaxf(s, 0.0f);
    }
    __syncthreads();
    if (tid < 4) {
        float s = pb3[tid];
        #pragma unroll
        for (int k = 0; k < 32; k++) s += h2[k] * P3[k * 4 + tid];
        val[tid] = softplusf(s + 2.0f);
    }
    __syncthreads();
    if (tid == 0) {
        float amin = 1.0f + val[0];
        out[0] = amin;
        out[1] = amin + val[1] + 0.5f;
        float bmin = 1.0f + val[2];
        out[2] = bmin;
        out[3] = bmin + val[3] + 0.5f;
    }
    if (tid < 24) out[4 + tid] = emb[tid];
}

// ---------------------------------------------------------------------------
extern "C" void kernel_launch(void* const* d_in, const int* in_sizes, int n_in,
                              void* d_out, int out_size) {
    const float* x   = (const float*)d_in[0];
    const int*   ei  = (const int*)d_in[1];
    const float* T   = (const float*)d_in[2];
    const float* Tm  = (const float*)d_in[3];
    const float* W1  = (const float*)d_in[4];
    const float* b1  = (const float*)d_in[5];
    const float* W2  = (const float*)d_in[6];
    const float* b2  = (const float*)d_in[7];
    const float* W3  = (const float*)d_in[8];
    const float* b3  = (const float*)d_in[9];
    const float* P1  = (const float*)d_in[10];
    const float* pb1 = (const float*)d_in[11];
    const float* P2  = (const float*)d_in[12];
    const float* pb2 = (const float*)d_in[13];
    const float* P3  = (const float*)d_in[14];
    const float* pb3 = (const float*)d_in[15];
    float* out = (float*)d_out;

    void *pCUR, *pGST;
    cudaGetSymbolAddress(&pCUR, CUR);
    cudaGetSymbolAddress(&pGST, GSTATS);
    cudaMemsetAsync(pCUR, 0, NN * sizeof(int));
    cudaMemsetAsync(pGST, 0, 32 * sizeof(float));

    k_place<<<(NE + 255) / 256, 256>>>(ei);
    k_xw1<<<NN / 8, 256>>>(x, W1);
    k_gl2<<<782, 256>>>(W2, b1);          // 6250 groups of 16 nodes, 8 warps/block
    k_gl3<<<782, 256>>>(W3, b2);
    k_gr<<<2344, 256>>>(ei);
    k_mlp<<<1, 64>>>(T, Tm, b3, P1, pb1, P2, pb2, P3, pb3, out);
}

// round 11
// speedup vs baseline: 1.0680x; 1.0680x over previous
#include <cuda_runtime.h>
#include <cuda_fp16.h>

#define NN 100000
#define NE 1200000
#define ELLW 64      // max degree capacity (Poisson(12): P(d>=64) ~ 1e-30)
#define APITCH 36    // uint (half2) pitch per smem row: 144 B, LDSM conflict-free

// Scratch (device globals — no allocation allowed). Row NN of HA/HB is all-zero.
__device__ unsigned HA[(size_t)(NN + 1) * 32];
__device__ unsigned HB[(size_t)(NN + 1) * 32];
__device__ unsigned H3[(size_t)NN * 8];    // layer-3 g, fp16x2 (16 feats)
__device__ int   ESRC[(size_t)NN * ELLW];  // ELL: src ids grouped by dst
__device__ int   CUR[NN];                  // slot counter == degree after place
__device__ float DINV[NN];
__device__ float GSTATS[32];               // [0..4] x-stats, [8..23] embedding sums

// ---------------------------------------------------------------------------
__global__ void k_place(const int* __restrict__ ei) {
    int e = blockIdx.x * blockDim.x + threadIdx.x;
    if (e < NE) {
        int src = ei[e], dst = ei[NE + e];
        int c = atomicAdd(&CUR[dst], 1);
        if (c < ELLW) ESRC[dst * ELLW + c] = src;
    }
}

// Layer 1 + dinv + x-stats. Warp per node, lane = feat pair. Also zeroes row NN.
__global__ void k_xw1(const float* __restrict__ x, const float* __restrict__ W1) {
    __shared__ float2 W1s[160];
    __shared__ float bins[5];
    int t = threadIdx.x;
    if (t < 160) W1s[t] = ((const float2*)W1)[t];
    if (t < 5) bins[t] = 0.0f;
    if (blockIdx.x == 0 && t < 32) { HA[NN * 32 + t] = 0; HB[NN * 32 + t] = 0; }
    __syncthreads();
    int lane = t & 31, w = t >> 5;
    int node = blockIdx.x * 8 + w;
    float di = rsqrtf((float)CUR[node] + 1.0f);
    float xv = (lane < 5) ? x[node * 5 + lane] : 0.0f;
    float2 s = make_float2(0.f, 0.f);
    float xs[5];
    #pragma unroll
    for (int i = 0; i < 5; i++) {
        float xi = __shfl_sync(0xffffffffu, xv, i);
        xs[i] = xi;
        float2 wv = W1s[i * 32 + lane];
        s.x += xi * wv.x; s.y += xi * wv.y;
    }
    if (lane == 0) {
        DINV[node] = di;
        atomicAdd(&bins[0], xs[2]);
        atomicAdd(&bins[1], xs[3]);
        atomicAdd(&bins[2], xs[4]);
        atomicAdd(&bins[3], xs[0] * xs[2]);
        atomicAdd(&bins[4], xs[1] * xs[2]);
    }
    __half2 o = __floats2half2_rn(s.x * di, s.y * di);
    HA[node * 32 + lane] = *(unsigned*)&o;
    __syncthreads();
    if (t < 5) atomicAdd(&GSTATS[t], bins[t]);
}

__device__ __forceinline__ unsigned sm_u32(const void* p) {
    return (unsigned)__cvta_generic_to_shared(p);
}

__device__ __forceinline__ void hacc4(__half2& a0, __half2& a1, __half2& a2, __half2& a3,
                                      const uint4& v) {
    a0 = __hadd2(a0, ((const __half2*)&v)[0]);
    a1 = __hadd2(a1, ((const __half2*)&v)[1]);
    a2 = __hadd2(a2, ((const __half2*)&v)[2]);
    a3 = __hadd2(a3, ((const __half2*)&v)[3]);
}

// Warp gathers 4 consecutive nodes (8 lanes/node, uint4/lane = 8 feats).
// 8 indices broadcast up front; loads in two half-batches of 4 to bound regs.
__device__ __forceinline__ void gather4_to_tile(
    const uint4* __restrict__ H4,       // (NN+1) x 8 uint4, row NN zero
    const float2* __restrict__ bs2,     // bias, 32 float2 (smem)
    int node0, int lane,
    unsigned* Arow,                     // &Aw[r * APITCH]
    float* dis)                         // &Dis[grp][r]
{
    int g = lane >> 3, u = lane & 7;
    int node = node0 + g;
    int d = CUR[node]; if (d > ELLW) d = ELLW;
    float di = DINV[node];
    uint4 v = H4[node * 8 + u];
    __half2 a0 = ((__half2*)&v)[0], a1 = ((__half2*)&v)[1];
    __half2 a2 = ((__half2*)&v)[2], a3 = ((__half2*)&v)[3];
    int dmax = d;
    dmax = max(dmax, __shfl_xor_sync(0xffffffffu, dmax, 8));
    dmax = max(dmax, __shfl_xor_sync(0xffffffffu, dmax, 16));
    const int* row = &ESRC[node * ELLW];
    for (int base = 0; base < dmax; base += 8) {
        int idxv = (base + u < d) ? row[base + u] : NN;   // NN = zero row
        int s0 = __shfl_sync(0xffffffffu, idxv, 0, 8);
        int s1 = __shfl_sync(0xffffffffu, idxv, 1, 8);
        int s2 = __shfl_sync(0xffffffffu, idxv, 2, 8);
        int s3 = __shfl_sync(0xffffffffu, idxv, 3, 8);
        int s4 = __shfl_sync(0xffffffffu, idxv, 4, 8);
        int s5 = __shfl_sync(0xffffffffu, idxv, 5, 8);
        int s6 = __shfl_sync(0xffffffffu, idxv, 6, 8);
        int s7 = __shfl_sync(0xffffffffu, idxv, 7, 8);
        {
            uint4 n0 = H4[s0 * 8 + u];
            uint4 n1 = H4[s1 * 8 + u];
            uint4 n2 = H4[s2 * 8 + u];
            uint4 n3 = H4[s3 * 8 + u];
            hacc4(a0, a1, a2, a3, n0);
            hacc4(a0, a1, a2, a3, n1);
            hacc4(a0, a1, a2, a3, n2);
            hacc4(a0, a1, a2, a3, n3);
        }
        {
            uint4 n4 = H4[s4 * 8 + u];
            uint4 n5 = H4[s5 * 8 + u];
            uint4 n6 = H4[s6 * 8 + u];
            uint4 n7 = H4[s7 * 8 + u];
            hacc4(a0, a1, a2, a3, n4);
            hacc4(a0, a1, a2, a3, n5);
            hacc4(a0, a1, a2, a3, n6);
            hacc4(a0, a1, a2, a3, n7);
        }
    }
    uint4 o;
    {
        float2 b = bs2[u * 4 + 0], f = __half22float2(a0);
        __half2 h = __floats2half2_rn(fmaxf(di * f.x + b.x, 0.f), fmaxf(di * f.y + b.y, 0.f));
        o.x = *(unsigned*)&h;
    }
    {
        float2 b = bs2[u * 4 + 1], f = __half22float2(a1);
        __half2 h = __floats2half2_rn(fmaxf(di * f.x + b.x, 0.f), fmaxf(di * f.y + b.y, 0.f));
        o.y = *(unsigned*)&h;
    }
    {
        float2 b = bs2[u * 4 + 2], f = __half22float2(a2);
        __half2 h = __floats2half2_rn(fmaxf(di * f.x + b.x, 0.f), fmaxf(di * f.y + b.y, 0.f));
        o.z = *(unsigned*)&h;
    }
    {
        float2 b = bs2[u * 4 + 3], f = __half22float2(a3);
        __half2 h = __floats2half2_rn(fmaxf(di * f.x + b.x, 0.f), fmaxf(di * f.y + b.y, 0.f));
        o.w = *(unsigned*)&h;
    }
    *(uint4*)&Arow[g * APITCH + u * 4] = o;
    if (u == 0) dis[g] = di;
}

// gl2: warp-pair per 16-node group. Each warp gathers 8 nodes, pair-barrier,
// both warps HMMA (split nt), -> HB. 512 threads, 8 groups/block.
__global__ void __launch_bounds__(512, 2) k_gl2(const float* __restrict__ W2,
                                                const float* __restrict__ b1) {
    __shared__ unsigned As[8][16 * APITCH];
    __shared__ unsigned W2h[64 * APITCH];
    __shared__ float    Dis[8][16];
    __shared__ float2   b1s[32];
    int t = threadIdx.x;
    for (int idx = t; idx < 2048; idx += 512) {
        int k = idx >> 5, np = idx & 31;
        __half2 wv = __floats2half2_rn(W2[k * 64 + 2 * np], W2[k * 64 + 2 * np + 1]);
        W2h[k * APITCH + np] = *(unsigned*)&wv;
    }
    if (t < 32) b1s[t] = ((const float2*)b1)[t];
    __syncthreads();
    int lane = t & 31, w = t >> 5;
    int grp = w >> 1, half = w & 1;
    int gw = blockIdx.x * 8 + grp;
    if (gw >= NN / 16) return;
    int gbase = gw * 16;
    unsigned* Aw = As[grp];

    // This warp gathers its 8 rows (half*8 .. half*8+7)
    {
        int r0 = half * 8;
        gather4_to_tile((const uint4*)HA, b1s, gbase + r0,     lane, &Aw[r0 * APITCH],       &Dis[grp][r0]);
        gather4_to_tile((const uint4*)HA, b1s, gbase + r0 + 4, lane, &Aw[(r0 + 4) * APITCH], &Dis[grp][r0 + 4]);
    }
    asm volatile("bar.sync %0, 64;" :: "r"(1 + grp) : "memory");

    unsigned a0[4], a1[4], a2[4], a3[4];
    {
        int tt = lane >> 3, i = lane & 7;
        int ar = i + ((tt & 1) << 3);
        #pragma unroll
        for (int ks = 0; ks < 4; ks++) {
            unsigned addr = sm_u32(&Aw[ar * APITCH + ks * 8 + ((tt >> 1) << 2)]);
            asm volatile("ldmatrix.sync.aligned.m8n8.x4.shared.b16 {%0,%1,%2,%3}, [%4];"
                         : "=r"(a0[ks]), "=r"(a1[ks]), "=r"(a2[ks]), "=r"(a3[ks])
                         : "r"(addr));
        }
    }
    float di0 = Dis[grp][lane >> 2];
    float di1 = Dis[grp][(lane >> 2) + 8];
    int n0 = gbase + (lane >> 2);
    int n1 = n0 + 8;
    int bl = lane & 15;
    int bi = bl & 7, bh = (bl >> 3) & 1;

    int ntb = half * 4;
    #pragma unroll
    for (int q = 0; q < 4; q++) {
        int nt = ntb + q;
        float d0 = 0.f, d1 = 0.f, d2 = 0.f, d3 = 0.f;
        #pragma unroll
        for (int ks = 0; ks < 4; ks++) {
            unsigned b0, b1r;
            unsigned baddr = sm_u32(&W2h[(ks * 16 + bh * 8 + bi) * APITCH + nt * 4]);
            asm volatile("ldmatrix.sync.aligned.m8n8.x2.trans.shared.b16 {%0,%1}, [%2];"
                         : "=r"(b0), "=r"(b1r) : "r"(baddr));
            asm volatile("mma.sync.aligned.m16n8k16.row.col.f32.f16.f16.f32 "
                         "{%0,%1,%2,%3}, {%4,%5,%6,%7}, {%8,%9}, {%0,%1,%2,%3};"
                         : "+f"(d0), "+f"(d1), "+f"(d2), "+f"(d3)
                         : "r"(a0[ks]), "r"(a1[ks]), "r"(a2[ks]), "r"(a3[ks]),
                           "r"(b0), "r"(b1r));
        }
        __half2 h0 = __floats2half2_rn(d0 * di0, d1 * di0);
        __half2 h1 = __floats2half2_rn(d2 * di1, d3 * di1);
        HB[n0 * 32 + nt * 4 + (lane & 3)] = *(unsigned*)&h0;
        HB[n1 * 32 + nt * 4 + (lane & 3)] = *(unsigned*)&h1;
    }
}

// gl3: warp-pair per 16-node group; HMMA 16x16x64 split by nt; -> H3 + self term.
__global__ void __launch_bounds__(512, 2) k_gl3(const float* __restrict__ W3,
                                                const float* __restrict__ b2) {
    __shared__ unsigned As[8][16 * APITCH];
    __shared__ unsigned W3h[64 * APITCH];
    __shared__ float    Dis[8][16];
    __shared__ float2   b2s[32];
    __shared__ float    sbin[16];
    int t = threadIdx.x;
    for (int idx = t; idx < 512; idx += 512) {
        int k = idx >> 3, p = idx & 7;
        __half2 wv = __floats2half2_rn(W3[k * 16 + 2 * p], W3[k * 16 + 2 * p + 1]);
        W3h[k * APITCH + p] = *(unsigned*)&wv;
    }
    if (t < 16) sbin[t] = 0.0f;
    if (t < 32) b2s[t] = ((const float2*)b2)[t];
    __syncthreads();
    int lane = t & 31, w = t >> 5;
    int grp = w >> 1, half = w & 1;
    int gw = blockIdx.x * 8 + grp;
    if (gw < NN / 16) {
        int gbase = gw * 16;
        unsigned* Aw = As[grp];
        {
            int r0 = half * 8;
            gather4_to_tile((const uint4*)HB, b2s, gbase + r0,     lane, &Aw[r0 * APITCH],       &Dis[grp][r0]);
            gather4_to_tile((const uint4*)HB, b2s, gbase + r0 + 4, lane, &Aw[(r0 + 4) * APITCH], &Dis[grp][r0 + 4]);
        }
        asm volatile("bar.sync %0, 64;" :: "r"(1 + grp) : "memory");

        unsigned a0[4], a1[4], a2[4], a3[4];
        {
            int tt = lane >> 3, i = lane & 7;
            int ar = i + ((tt & 1) << 3);
            #pragma unroll
            for (int ks = 0; ks < 4; ks++) {
                unsigned addr = sm_u32(&Aw[ar * APITCH + ks * 8 + ((tt >> 1) << 2)]);
                asm volatile("ldmatrix.sync.aligned.m8n8.x4.shared.b16 {%0,%1,%2,%3}, [%4];"
                             : "=r"(a0[ks]), "=r"(a1[ks]), "=r"(a2[ks]), "=r"(a3[ks])
                             : "r"(addr));
            }
        }
        float di0 = Dis[grp][lane >> 2];
        float di1 = Dis[grp][(lane >> 2) + 8];
        int n0 = gbase + (lane >> 2);
        int n1 = n0 + 8;
        int bl = lane & 15;
        int bi = bl & 7, bh = (bl >> 3) & 1;

        int nt = half;   // warp half owns one 8-col n-tile
        float d0 = 0.f, d1 = 0.f, d2 = 0.f, d3 = 0.f;
        #pragma unroll
        for (int ks = 0; ks < 4; ks++) {
            unsigned b0, b1r;
            unsigned baddr = sm_u32(&W3h[(ks * 16 + bh * 8 + bi) * APITCH + nt * 4]);
            asm volatile("ldmatrix.sync.aligned.m8n8.x2.trans.shared.b16 {%0,%1}, [%2];"
                         : "=r"(b0), "=r"(b1r) : "r"(baddr));
            asm volatile("mma.sync.aligned.m16n8k16.row.col.f32.f16.f16.f32 "
                         "{%0,%1,%2,%3}, {%4,%5,%6,%7}, {%8,%9}, {%0,%1,%2,%3};"
                         : "+f"(d0), "+f"(d1), "+f"(d2), "+f"(d3)
                         : "r"(a0[ks]), "r"(a1[ks]), "r"(a2[ks]), "r"(a3[ks]),
                           "r"(b0), "r"(b1r));
        }
        float g0 = d0 * di0, g1 = d1 * di0, g2 = d2 * di1, g3v = d3 * di1;
        __half2 h0 = __floats2half2_rn(g0, g1);
        __half2 h1 = __floats2half2_rn(g2, g3v);
        H3[n0 * 8 + nt * 4 + (lane & 3)] = *(unsigned*)&h0;
        H3[n1 * 8 + nt * 4 + (lane & 3)] = *(unsigned*)&h1;
        float s0 = g0 * di0 + g2 * di1;
        float s1 = g1 * di0 + g3v * di1;
        int j0 = 8 * half + 2 * (lane & 3);
        atomicAdd(&sbin[j0],     s0);
        atomicAdd(&sbin[j0 + 1], s1);
    }
    __syncthreads();
    if (t < 16) atomicAdd(&GSTATS[8 + t], sbin[t]);
}

// Edge-parallel final reduce: sum_e g3[src] * dinv[dst]. 8 lanes/edge, 4 edges/warp.
__global__ void k_gr(const int* __restrict__ ei) {
    __shared__ float sbin[16];
    int t = threadIdx.x;
    if (t < 16) sbin[t] = 0.0f;
    __syncthreads();
    int u = t & 7;
    int slot = (t >> 3) & 3;
    int gw = blockIdx.x * 8 + (t >> 5);
    int eb = gw * 64 + slot;
    float2 acc = make_float2(0.f, 0.f);
    #pragma unroll 4
    for (int it = 0; it < 16; it++) {
        int e = eb + it * 4;
        if (e < NE) {
            int src = ei[e], dst = ei[NE + e];
            unsigned v = H3[src * 8 + u];
            float2 f = __half22float2(*(__half2*)&v);
            float dd = DINV[dst];
            acc.x += f.x * dd; acc.y += f.y * dd;
        }
    }
    atomicAdd(&sbin[2 * u], acc.x);
    atomicAdd(&sbin[2 * u + 1], acc.y);
    __syncthreads();
    if (t < 16) atomicAdd(&GSTATS[8 + t], sbin[t]);
}

__device__ __forceinline__ float softplusf(float v) {
    return fmaxf(v, 0.0f) + log1pf(expf(-fabsf(v)));
}

// Final MLP head, single block of 64 threads
__global__ void k_mlp(const float* __restrict__ T, const float* __restrict__ Tm,
                      const float* __restrict__ b3,
                      const float* __restrict__ P1, const float* __restrict__ pb1,
                      const float* __restrict__ P2, const float* __restrict__ pb2,
                      const float* __restrict__ P3, const float* __restrict__ pb3,
                      float* __restrict__ out) {
    __shared__ float emb[24], h1[64], h2[32], val[4];
    int tid = threadIdx.x;
    if (tid < 16) emb[tid] = GSTATS[8 + tid] * (1.0f / NN) + b3[tid];
    if (tid == 0) {
        float ncomp = GSTATS[0], nAND = GSTATS[1], nOR = GSTATS[2];
        float slam = GSTATS[3], smu = GSTATS[4];
        float Tn = T[0] / Tm[0];
        float safe = fmaxf(ncomp, 1.0f);
        bool has = ncomp > 0.0f;
        emb[16] = ncomp; emb[17] = nAND; emb[18] = nOR; emb[19] = nAND + nOR;
        emb[20] = has ? slam / safe : 0.0f;
        emb[21] = has ? smu / safe : 0.0f;
        emb[22] = Tn * 50.0f;
        emb[23] = (1.0f / (1.0f + Tn)) * 50.0f;
    }
    __syncthreads();
    {
        float s = pb1[tid];
        #pragma unroll
        for (int k = 0; k < 24; k++) s += emb[k] * P1[k * 64 + tid];
        h1[tid] = fmaxf(s, 0.0f);
    }
    __syncthreads();
    if (tid < 32) {
        float s = pb2[tid];
        #pragma unroll
        for (int k = 0; k < 64; k++) s += h1[k] * P2[k * 32 + tid];
        h2[tid] = fmaxf(s, 0.0f);
    }
    __syncthreads();
    if (tid < 4) {
        float s = pb3[tid];
        #pragma unroll
        for (int k = 0; k < 32; k++) s += h2[k] * P3[k * 4 + tid];
        val[tid] = softplusf(s + 2.0f);
    }
    __syncthreads();
    if (tid == 0) {
        float amin = 1.0f + val[0];
        out[0] = amin;
        out[1] = amin + val[1] + 0.5f;
        float bmin = 1.0f + val[2];
        out[2] = bmin;
        out[3] = bmin + val[3] + 0.5f;
    }
    if (tid < 24) out[4 + tid] = emb[tid];
}

// ---------------------------------------------------------------------------
extern "C" void kernel_launch(void* const* d_in, const int* in_sizes, int n_in,
                              void* d_out, int out_size) {
    const float* x   = (const float*)d_in[0];
    const int*   ei  = (const int*)d_in[1];
    const float* T   = (const float*)d_in[2];
    const float* Tm  = (const float*)d_in[3];
    const float* W1  = (const float*)d_in[4];
    const float* b1  = (const float*)d_in[5];
    const float* W2  = (const float*)d_in[6];
    const float* b2  = (const float*)d_in[7];
    const float* W3  = (const float*)d_in[8];
    const float* b3  = (const float*)d_in[9];
    const float* P1  = (const float*)d_in[10];
    const float* pb1 = (const float*)d_in[11];
    const float* P2  = (const float*)d_in[12];
    const float* pb2 = (const float*)d_in[13];
    const float* P3  = (const float*)d_in[14];
    const float* pb3 = (const float*)d_in[15];
    float* out = (float*)d_out;

    void *pCUR, *pGST;
    cudaGetSymbolAddress(&pCUR, CUR);
    cudaGetSymbolAddress(&pGST, GSTATS);
    cudaMemsetAsync(pCUR, 0, NN * sizeof(int));
    cudaMemsetAsync(pGST, 0, 32 * sizeof(float));

    k_place<<<(NE + 255) / 256, 256>>>(ei);
    k_xw1<<<NN / 8, 256>>>(x, W1);
    k_gl2<<<782, 512>>>(W2, b1);          // 8 groups/block, warp-pair per group
    k_gl3<<<782, 512>>>(W3, b2);
    k_gr<<<2344, 256>>>(ei);
    k_mlp<<<1, 64>>>(T, Tm, b3, P1, pb1, P2, pb2, P3, pb3, out);
}

// round 14
// speedup vs baseline: 1.1450x; 1.0721x over previous
#include <cuda_runtime.h>
#include <cuda_fp16.h>

#define NN 100000
#define NE 1200000
#define ELLW 64      // max degree capacity (Poisson(12): P(d>=64) ~ 1e-30)
#define APITCH 36    // uint (half2) pitch per smem A-tile row: 144 B, LDSM conflict-free

// Scratch. HA8/HB8: fp8 e4m3 feature tables, 64 B/row; row NN is all-zero.
__device__ unsigned HA8[(size_t)(NN + 1) * 16];
__device__ unsigned HB8[(size_t)(NN + 1) * 16];
__device__ unsigned H3[(size_t)NN * 8];    // layer-3 g, fp16x2 (16 feats)
__device__ int   ESRC[(size_t)NN * ELLW];  // ELL: src ids grouped by dst
__device__ int   CUR[NN];                  // slot counter == degree after place
__device__ float DINV[NN];
__device__ float GSTATS[32];               // [0..4] x-stats, [8..23] embedding sums

// ---------------------------------------------------------------------------
__global__ void k_place(const int* __restrict__ ei) {
    int e = blockIdx.x * blockDim.x + threadIdx.x;
    if (e < NE) {
        int src = ei[e], dst = ei[NE + e];
        int c = atomicAdd(&CUR[dst], 1);
        if (c < ELLW) ESRC[dst * ELLW + c] = src;
    }
}

__device__ __forceinline__ unsigned short e4m3pack(float hi, float lo) {
    unsigned short r;
    asm("cvt.rn.satfinite.e4m3x2.f32 %0, %1, %2;" : "=h"(r) : "f"(hi), "f"(lo));
    return r;
}

// Layer 1 + dinv + x-stats. Warp per node, lane = feat pair. Zeroes row NN.
__global__ void k_xw1(const float* __restrict__ x, const float* __restrict__ W1) {
    __shared__ float2 W1s[160];
    __shared__ float bins[5];
    int t = threadIdx.x;
    if (t < 160) W1s[t] = ((const float2*)W1)[t];
    if (t < 5) bins[t] = 0.0f;
    if (blockIdx.x == 0 && t < 16) { HA8[NN * 16 + t] = 0; HB8[NN * 16 + t] = 0; }
    __syncthreads();
    int lane = t & 31, w = t >> 5;
    int node = blockIdx.x * 8 + w;
    float di = rsqrtf((float)CUR[node] + 1.0f);
    float xv = (lane < 5) ? x[node * 5 + lane] : 0.0f;
    float2 s = make_float2(0.f, 0.f);
    float xs[5];
    #pragma unroll
    for (int i = 0; i < 5; i++) {
        float xi = __shfl_sync(0xffffffffu, xv, i);
        xs[i] = xi;
        float2 wv = W1s[i * 32 + lane];
        s.x += xi * wv.x; s.y += xi * wv.y;
    }
    if (lane == 0) {
        DINV[node] = di;
        atomicAdd(&bins[0], xs[2]);
        atomicAdd(&bins[1], xs[3]);
        atomicAdd(&bins[2], xs[4]);
        atomicAdd(&bins[3], xs[0] * xs[2]);
        atomicAdd(&bins[4], xs[1] * xs[2]);
    }
    ((unsigned short*)HA8)[node * 32 + lane] = e4m3pack(s.y * di, s.x * di);
    __syncthreads();
    if (t < 5) atomicAdd(&GSTATS[t], bins[t]);
}

__device__ __forceinline__ unsigned sm_u32(const void* p) {
    return (unsigned)__cvta_generic_to_shared(p);
}

__device__ __forceinline__ void fcvt_acc(unsigned w, __half2& x, __half2& y) {
    unsigned lo, hi;
    unsigned short wl = (unsigned short)(w & 0xffffu);
    unsigned short wh = (unsigned short)(w >> 16);
    asm("cvt.rn.f16x2.e4m3x2 %0, %1;" : "=r"(lo) : "h"(wl));
    asm("cvt.rn.f16x2.e4m3x2 %0, %1;" : "=r"(hi) : "h"(wh));
    x = __hadd2(x, *(__half2*)&lo);
    y = __hadd2(y, *(__half2*)&hi);
}

__device__ __forceinline__ void fcvt_set(unsigned w, __half2& x, __half2& y) {
    unsigned lo, hi;
    unsigned short wl = (unsigned short)(w & 0xffffu);
    unsigned short wh = (unsigned short)(w >> 16);
    asm("cvt.rn.f16x2.e4m3x2 %0, %1;" : "=r"(lo) : "h"(wl));
    asm("cvt.rn.f16x2.e4m3x2 %0, %1;" : "=r"(hi) : "h"(wh));
    x = *(__half2*)&lo;
    y = *(__half2*)&hi;
}

__device__ __forceinline__ void fold16(const uint4& v, __half2* a) {
    fcvt_acc(v.x, a[0], a[1]);
    fcvt_acc(v.y, a[2], a[3]);
    fcvt_acc(v.z, a[4], a[5]);
    fcvt_acc(v.w, a[6], a[7]);
}

// Warp gathers 8 consecutive nodes (4 lanes/node, uint4/lane = 16 fp8 feats).
// Batches of 4 neighbor slots; one warp-LDG covers 8 rows; index prefetch.
__device__ __forceinline__ void gather8_to_tile(
    const uint4* __restrict__ H4,       // (NN+1) x 4 uint4, row NN zero
    const float2* __restrict__ bs2,     // bias, 32 float2 (smem)
    int node0, int lane,
    unsigned* Arows,                    // A-tile rows base (rows relative to node0)
    float* dis)
{
    int g = lane >> 2, u = lane & 3;    // 8 groups x 4 lanes
    int node = node0 + g;
    int d = CUR[node]; if (d > ELLW) d = ELLW;
    float di = DINV[node];
    __half2 acc[8];
    {
        uint4 v = H4[node * 4 + u];     // self row
        fcvt_set(v.x, acc[0], acc[1]);
        fcvt_set(v.y, acc[2], acc[3]);
        fcvt_set(v.z, acc[4], acc[5]);
        fcvt_set(v.w, acc[6], acc[7]);
    }
    int dmax = d;
    dmax = max(dmax, __shfl_xor_sync(0xffffffffu, dmax, 4));
    dmax = max(dmax, __shfl_xor_sync(0xffffffffu, dmax, 8));
    dmax = max(dmax, __shfl_xor_sync(0xffffffffu, dmax, 16));
    const int* row = &ESRC[node * ELLW];
    int pf = (u < d) ? row[u] : NN;     // prefetched indices for current batch
    for (int base = 0; base < dmax; base += 4) {
        int idxv = pf;
        int nb = base + 4;
        if (nb < dmax) pf = (nb + u < d) ? row[nb + u] : NN;
        int s0 = __shfl_sync(0xffffffffu, idxv, 0, 4);
        int s1 = __shfl_sync(0xffffffffu, idxv, 1, 4);
        int s2 = __shfl_sync(0xffffffffu, idxv, 2, 4);
        int s3 = __shfl_sync(0xffffffffu, idxv, 3, 4);
        uint4 n0 = H4[s0 * 4 + u];
        uint4 n1 = H4[s1 * 4 + u];
        uint4 n2 = H4[s2 * 4 + u];
        uint4 n3 = H4[s3 * 4 + u];
        fold16(n0, acc);
        fold16(n1, acc);
        fold16(n2, acc);
        fold16(n3, acc);
    }
    uint4 o0, o1;
    unsigned* po0 = (unsigned*)&o0;
    unsigned* po1 = (unsigned*)&o1;
    #pragma unroll
    for (int p = 0; p < 8; p++) {
        float2 b = bs2[u * 8 + p];
        float2 f = __half22float2(acc[p]);
        __half2 h = __floats2half2_rn(fmaxf(di * f.x + b.x, 0.f),
                                      fmaxf(di * f.y + b.y, 0.f));
        if (p < 4) po0[p] = *(unsigned*)&h; else po1[p - 4] = *(unsigned*)&h;
    }
    *(uint4*)&Arows[g * APITCH + u * 8] = o0;
    *(uint4*)&Arows[g * APITCH + u * 8 + 4] = o1;
    if (u == 0) dis[g] = di;
}

// gl2: warp-pair per 16-node group; each warp gathers 8 nodes (fp8 HA8),
// pair-barrier, HMMA 16x64x64 split by nt, -> HB8 (fp8).
__global__ void __launch_bounds__(512, 2) k_gl2(const float* __restrict__ W2,
                                                const float* __restrict__ b1) {
    __shared__ unsigned As[8][16 * APITCH];
    __shared__ unsigned W2h[64 * APITCH];
    __shared__ float    Dis[8][16];
    __shared__ float2   b1s[32];
    int t = threadIdx.x;
    for (int idx = t; idx < 2048; idx += 512) {
        int k = idx >> 5, np = idx & 31;
        __half2 wv = __floats2half2_rn(W2[k * 64 + 2 * np], W2[k * 64 + 2 * np + 1]);
        W2h[k * APITCH + np] = *(unsigned*)&wv;
    }
    if (t < 32) b1s[t] = ((const float2*)b1)[t];
    __syncthreads();
    int lane = t & 31, w = t >> 5;
    int grp = w >> 1, half = w & 1;
    int gw = blockIdx.x * 8 + grp;
    if (gw >= NN / 16) return;
    int gbase = gw * 16;
    unsigned* Aw = As[grp];

    gather8_to_tile((const uint4*)HA8, b1s, gbase + 8 * half, lane,
                    Aw + (8 * half) * APITCH, &Dis[grp][8 * half]);
    asm volatile("bar.sync %0, 64;" :: "r"(1 + grp) : "memory");

    unsigned a0[4], a1[4], a2[4], a3[4];
    {
        int tt = lane >> 3, i = lane & 7;
        int ar = i + ((tt & 1) << 3);
        #pragma unroll
        for (int ks = 0; ks < 4; ks++) {
            unsigned addr = sm_u32(&Aw[ar * APITCH + ks * 8 + ((tt >> 1) << 2)]);
            asm volatile("ldmatrix.sync.aligned.m8n8.x4.shared.b16 {%0,%1,%2,%3}, [%4];"
                         : "=r"(a0[ks]), "=r"(a1[ks]), "=r"(a2[ks]), "=r"(a3[ks])
                         : "r"(addr));
        }
    }
    float di0 = Dis[grp][lane >> 2];
    float di1 = Dis[grp][(lane >> 2) + 8];
    int n0 = gbase + (lane >> 2);
    int n1 = n0 + 8;
    int bl = lane & 15;
    int bi = bl & 7, bh = (bl >> 3) & 1;

    int ntb = half * 4;
    #pragma unroll
    for (int q = 0; q < 4; q++) {
        int nt = ntb + q;
        float d0 = 0.f, d1 = 0.f, d2 = 0.f, d3 = 0.f;
        #pragma unroll
        for (int ks = 0; ks < 4; ks++) {
            unsigned b0, b1r;
            unsigned baddr = sm_u32(&W2h[(ks * 16 + bh * 8 + bi) * APITCH + nt * 4]);
            asm volatile("ldmatrix.sync.aligned.m8n8.x2.trans.shared.b16 {%0,%1}, [%2];"
                         : "=r"(b0), "=r"(b1r) : "r"(baddr));
            asm volatile("mma.sync.aligned.m16n8k16.row.col.f32.f16.f16.f32 "
                         "{%0,%1,%2,%3}, {%4,%5,%6,%7}, {%8,%9}, {%0,%1,%2,%3};"
                         : "+f"(d0), "+f"(d1), "+f"(d2), "+f"(d3)
                         : "r"(a0[ks]), "r"(a1[ks]), "r"(a2[ks]), "r"(a3[ks]),
                           "r"(b0), "r"(b1r));
        }
        ((unsigned short*)HB8)[n0 * 32 + nt * 4 + (lane & 3)] = e4m3pack(d1 * di0, d0 * di0);
        ((unsigned short*)HB8)[n1 * 32 + nt * 4 + (lane & 3)] = e4m3pack(d3 * di1, d2 * di1);
    }
}

// gl3: warp-pair per 16-node group; fp8 HB8 gather; HMMA 16x16x64 split by nt;
// -> H3 (fp16) + self term into GSTATS.
__global__ void __launch_bounds__(512, 2) k_gl3(const float* __restrict__ W3,
                                                const float* __restrict__ b2) {
    __shared__ unsigned As[8][16 * APITCH];
    __shared__ unsigned W3h[64 * APITCH];
    __shared__ float    Dis[8][16];
    __shared__ float2   b2s[32];
    __shared__ float    sbin[16];
    int t = threadIdx.x;
    for (int idx = t; idx < 512; idx += 512) {
        int k = idx >> 3, p = idx & 7;
        __half2 wv = __floats2half2_rn(W3[k * 16 + 2 * p], W3[k * 16 + 2 * p + 1]);
        W3h[k * APITCH + p] = *(unsigned*)&wv;
    }
    if (t < 16) sbin[t] = 0.0f;
    if (t < 32) b2s[t] = ((const float2*)b2)[t];
    __syncthreads();
    int lane = t & 31, w = t >> 5;
    int grp = w >> 1, half = w & 1;
    int gw = blockIdx.x * 8 + grp;
    if (gw < NN / 16) {
        int gbase = gw * 16;
        unsigned* Aw = As[grp];
        gather8_to_tile((const uint4*)HB8, b2s, gbase + 8 * half, lane,
                        Aw + (8 * half) * APITCH, &Dis[grp][8 * half]);
        asm volatile("bar.sync %0, 64;" :: "r"(1 + grp) : "memory");

        unsigned a0[4], a1[4], a2[4], a3[4];
        {
            int tt = lane >> 3, i = lane & 7;
            int ar = i + ((tt & 1) << 3);
            #pragma unroll
            for (int ks = 0; ks < 4; ks++) {
                unsigned addr = sm_u32(&Aw[ar * APITCH + ks * 8 + ((tt >> 1) << 2)]);
                asm volatile("ldmatrix.sync.aligned.m8n8.x4.shared.b16 {%0,%1,%2,%3}, [%4];"
                             : "=r"(a0[ks]), "=r"(a1[ks]), "=r"(a2[ks]), "=r"(a3[ks])
                             : "r"(addr));
            }
        }
        float di0 = Dis[grp][lane >> 2];
        float di1 = Dis[grp][(lane >> 2) + 8];
        int n0 = gbase + (lane >> 2);
        int n1 = n0 + 8;
        int bl = lane & 15;
        int bi = bl & 7, bh = (bl >> 3) & 1;

        int nt = half;   // warp half owns one 8-col n-tile
        float d0 = 0.f, d1 = 0.f, d2 = 0.f, d3 = 0.f;
        #pragma unroll
        for (int ks = 0; ks < 4; ks++) {
            unsigned b0, b1r;
            unsigned baddr = sm_u32(&W3h[(ks * 16 + bh * 8 + bi) * APITCH + nt * 4]);
            asm volatile("ldmatrix.sync.aligned.m8n8.x2.trans.shared.b16 {%0,%1}, [%2];"
                         : "=r"(b0), "=r"(b1r) : "r"(baddr));
            asm volatile("mma.sync.aligned.m16n8k16.row.col.f32.f16.f16.f32 "
                         "{%0,%1,%2,%3}, {%4,%5,%6,%7}, {%8,%9}, {%0,%1,%2,%3};"
                         : "+f"(d0), "+f"(d1), "+f"(d2), "+f"(d3)
                         : "r"(a0[ks]), "r"(a1[ks]), "r"(a2[ks]), "r"(a3[ks]),
                           "r"(b0), "r"(b1r));
        }
        float g0 = d0 * di0, g1 = d1 * di0, g2 = d2 * di1, g3v = d3 * di1;
        __half2 h0 = __floats2half2_rn(g0, g1);
        __half2 h1 = __floats2half2_rn(g2, g3v);
        H3[n0 * 8 + nt * 4 + (lane & 3)] = *(unsigned*)&h0;
        H3[n1 * 8 + nt * 4 + (lane & 3)] = *(unsigned*)&h1;
        float s0 = g0 * di0 + g2 * di1;
        float s1 = g1 * di0 + g3v * di1;
        int j0 = 8 * half + 2 * (lane & 3);
        atomicAdd(&sbin[j0],     s0);
        atomicAdd(&sbin[j0 + 1], s1);
    }
    __syncthreads();
    if (t < 16) atomicAdd(&GSTATS[8 + t], sbin[t]);
}

// Edge-parallel final reduce: sum_e g3[src] * dinv[dst]. 8 lanes/edge, 4 edges/warp.
__global__ void k_gr(const int* __restrict__ ei) {
    __shared__ float sbin[16];
    int t = threadIdx.x;
    if (t < 16) sbin[t] = 0.0f;
    __syncthreads();
    int u = t & 7;
    int slot = (t >> 3) & 3;
    int gw = blockIdx.x * 8 + (t >> 5);
    int eb = gw * 64 + slot;
    float2 acc = make_float2(0.f, 0.f);
    #pragma unroll 4
    for (int it = 0; it < 16; it++) {
        int e = eb + it * 4;
        if (e < NE) {
            int src = ei[e], dst = ei[NE + e];
            unsigned v = H3[src * 8 + u];
            float2 f = __half22float2(*(__half2*)&v);
            float dd = DINV[dst];
            acc.x += f.x * dd; acc.y += f.y * dd;
        }
    }
    atomicAdd(&sbin[2 * u], acc.x);
    atomicAdd(&sbin[2 * u + 1], acc.y);
    __syncthreads();
    if (t < 16) atomicAdd(&GSTATS[8 + t], sbin[t]);
}

__device__ __forceinline__ float softplusf(float v) {
    return fmaxf(v, 0.0f) + log1pf(expf(-fabsf(v)));
}

// Final MLP head, single block of 64 threads
__global__ void k_mlp(const float* __restrict__ T, const float* __restrict__ Tm,
                      const float* __restrict__ b3,
                      const float* __restrict__ P1, const float* __restrict__ pb1,
                      const float* __restrict__ P2, const float* __restrict__ pb2,
                      const float* __restrict__ P3, const float* __restrict__ pb3,
                      float* __restrict__ out) {
    __shared__ float emb[24], h1[64], h2[32], val[4];
    int tid = threadIdx.x;
    if (tid < 16) emb[tid] = GSTATS[8 + tid] * (1.0f / NN) + b3[tid];
    if (tid == 0) {
        float ncomp = GSTATS[0], nAND = GSTATS[1], nOR = GSTATS[2];
        float slam = GSTATS[3], smu = GSTATS[4];
        float Tn = T[0] / Tm[0];
        float safe = fmaxf(ncomp, 1.0f);
        bool has = ncomp > 0.0f;
        emb[16] = ncomp; emb[17] = nAND; emb[18] = nOR; emb[19] = nAND + nOR;
        emb[20] = has ? slam / safe : 0.0f;
        emb[21] = has ? smu / safe : 0.0f;
        emb[22] = Tn * 50.0f;
        emb[23] = (1.0f / (1.0f + Tn)) * 50.0f;
    }
    __syncthreads();
    {
        float s = pb1[tid];
        #pragma unroll
        for (int k = 0; k < 24; k++) s += emb[k] * P1[k * 64 + tid];
        h1[tid] = fmaxf(s, 0.0f);
    }
    __syncthreads();
    if (tid < 32) {
        float s = pb2[tid];
        #pragma unroll
        for (int k = 0; k < 64; k++) s += h1[k] * P2[k * 32 + tid];
        h2[tid] = fmaxf(s, 0.0f);
    }
    __syncthreads();
    if (tid < 4) {
        float s = pb3[tid];
        #pragma unroll
        for (int k = 0; k < 32; k++) s += h2[k] * P3[k * 4 + tid];
        val[tid] = softplusf(s + 2.0f);
    }
    __syncthreads();
    if (tid == 0) {
        float amin = 1.0f + val[0];
        out[0] = amin;
        out[1] = amin + val[1] + 0.5f;
        float bmin = 1.0f + val[2];
        out[2] = bmin;
        out[3] = bmin + val[3] + 0.5f;
    }
    if (tid < 24) out[4 + tid] = emb[tid];
}

// ---------------------------------------------------------------------------
extern "C" void kernel_launch(void* const* d_in, const int* in_sizes, int n_in,
                              void* d_out, int out_size) {
    const float* x   = (const float*)d_in[0];
    const int*   ei  = (const int*)d_in[1];
    const float* T   = (const float*)d_in[2];
    const float* Tm  = (const float*)d_in[3];
    const float* W1  = (const float*)d_in[4];
    const float* b1  = (const float*)d_in[5];
    const float* W2  = (const float*)d_in[6];
    const float* b2  = (const float*)d_in[7];
    const float* W3  = (const float*)d_in[8];
    const float* b3  = (const float*)d_in[9];
    const float* P1  = (const float*)d_in[10];
    const float* pb1 = (const float*)d_in[11];
    const float* P2  = (const float*)d_in[12];
    const float* pb2 = (const float*)d_in[13];
    const float* P3  = (const float*)d_in[14];
    const float* pb3 = (const float*)d_in[15];
    float* out = (float*)d_out;

    void *pCUR, *pGST;
    cudaGetSymbolAddress(&pCUR, CUR);
    cudaGetSymbolAddress(&pGST, GSTATS);
    cudaMemsetAsync(pCUR, 0, NN * sizeof(int));
    cudaMemsetAsync(pGST, 0, 32 * sizeof(float));

    k_place<<<(NE + 255) / 256, 256>>>(ei);
    k_xw1<<<NN / 8, 256>>>(x, W1);
    k_gl2<<<782, 512>>>(W2, b1);          // 8 groups/block, warp-pair per group
    k_gl3<<<782, 512>>>(W3, b2);
    k_gr<<<2344, 256>>>(ei);
    k_mlp<<<1, 64>>>(T, Tm, b3, P1, pb1, P2, pb2, P3, pb3, out);
}

// round 15
// speedup vs baseline: 1.4810x; 1.2935x over previous
#include <cuda_runtime.h>
#include <cuda_fp16.h>

#define NN 100000
#define NE 1200000
#define ELLW 64      // max degree capacity (Poisson(12): P(d>=64) ~ 1e-30)
#define APITCH 36    // uint (half2) pitch per smem A-tile row: 144 B, LDSM conflict-free

// Scratch. XD: fp16 x*dinv rows (16 B, 5 used + 3 zero pad); row NN zero.
// HB8: fp8 e4m3 layer-2 feature table, 64 B/row; row NN zero.
__device__ unsigned XDraw[(size_t)(NN + 1) * 4];
__device__ unsigned HB8[(size_t)(NN + 1) * 16];
__device__ unsigned H3[(size_t)NN * 8];    // layer-3 g, fp16x2 (16 feats)
__device__ int   ESRC[(size_t)NN * ELLW];  // ELL: src ids grouped by dst
__device__ int   CUR[NN];                  // slot counter == degree after place
__device__ float DINV[NN];
__device__ float GSTATS[32];               // [0..4] x-stats, [8..23] embedding sums

// ---------------------------------------------------------------------------
__global__ void k_place(const int* __restrict__ ei) {
    if (blockIdx.x == 0 && threadIdx.x < 32) GSTATS[threadIdx.x] = 0.0f;
    int e = blockIdx.x * blockDim.x + threadIdx.x;
    if (e < NE) {
        int src = ei[e], dst = ei[NE + e];
        int c = atomicAdd(&CUR[dst], 1);
        if (c < ELLW) ESRC[dst * ELLW + c] = src;
    }
}

__device__ __forceinline__ unsigned short e4m3pack(float hi, float lo) {
    unsigned short r;
    asm("cvt.rn.satfinite.e4m3x2.f32 %0, %1, %2;" : "=h"(r) : "f"(hi), "f"(lo));
    return r;
}

__device__ __forceinline__ unsigned h2pack(float lo, float hi) {
    __half2 h = __floats2half2_rn(lo, hi);
    return *(unsigned*)&h;
}

// Prelude: XD = x*dinv (fp16, 16B row), DINV, x-stats. 1 thread/node.
__global__ void k_pre(const float* __restrict__ x) {
    __shared__ float bins[5];
    int t = threadIdx.x;
    if (t < 5) bins[t] = 0.0f;
    if (blockIdx.x == 0) {
        if (t < 4)  ((uint4*)XDraw)[NN].x = 0;   // lazy but correct: full row below
        if (t < 16) HB8[NN * 16 + t] = 0;
        if (t < 4)  XDraw[NN * 4 + t] = 0;
    }
    __syncthreads();
    int i = blockIdx.x * 256 + t;
    float s0 = 0.f, s1 = 0.f, s2 = 0.f, s3 = 0.f, s4 = 0.f;
    if (i < NN) {
        int dv = CUR[i];
        float di = rsqrtf((float)dv + 1.0f);
        DINV[i] = di;
        float lam = x[i * 5 + 0], mu = x[i * 5 + 1];
        float c = x[i * 5 + 2], a = x[i * 5 + 3], o = x[i * 5 + 4];
        uint4 r;
        r.x = h2pack(lam * di, mu * di);
        r.y = h2pack(c * di, a * di);
        r.z = h2pack(o * di, 0.0f);
        r.w = 0;
        ((uint4*)XDraw)[i] = r;
        s0 = c; s1 = a; s2 = o; s3 = lam * c; s4 = mu * c;
    }
    #pragma unroll
    for (int off = 16; off; off >>= 1) {
        s0 += __shfl_down_sync(0xffffffffu, s0, off);
        s1 += __shfl_down_sync(0xffffffffu, s1, off);
        s2 += __shfl_down_sync(0xffffffffu, s2, off);
        s3 += __shfl_down_sync(0xffffffffu, s3, off);
        s4 += __shfl_down_sync(0xffffffffu, s4, off);
    }
    if ((t & 31) == 0) {
        atomicAdd(&bins[0], s0);
        atomicAdd(&bins[1], s1);
        atomicAdd(&bins[2], s2);
        atomicAdd(&bins[3], s3);
        atomicAdd(&bins[4], s4);
    }
    __syncthreads();
    if (t < 5) atomicAdd(&GSTATS[t], bins[t]);
}

__device__ __forceinline__ unsigned sm_u32(const void* p) {
    return (unsigned)__cvta_generic_to_shared(p);
}

// gl2: warp-pair per 16-node group. Gather 5-dim XD (16B rows, 1 lane/edge,
// divergent per-lane loop), S@W1 on the fly -> A-tile, HMMA 16x64x64 -> HB8.
__global__ void __launch_bounds__(512, 2) k_gl2(const float* __restrict__ W1,
                                                const float* __restrict__ b1,
                                                const float* __restrict__ W2) {
    __shared__ unsigned As[8][16 * APITCH];
    __shared__ unsigned W2h[64 * APITCH];
    __shared__ uint4    Ssm[16][8];
    __shared__ float    Dis[8][16];
    __shared__ float2   W1s[160];
    __shared__ float2   b1s[32];
    int t = threadIdx.x;
    for (int idx = t; idx < 2048; idx += 512) {
        int k = idx >> 5, np = idx & 31;
        __half2 wv = __floats2half2_rn(W2[k * 64 + 2 * np], W2[k * 64 + 2 * np + 1]);
        W2h[k * APITCH + np] = *(unsigned*)&wv;
    }
    if (t < 160) W1s[t] = ((const float2*)W1)[t];
    if (t < 32) b1s[t] = ((const float2*)b1)[t];
    __syncthreads();
    int lane = t & 31, w = t >> 5;
    int grp = w >> 1, half = w & 1;
    int gw = blockIdx.x * 8 + grp;
    if (gw >= NN / 16) return;
    int gbase = gw * 16;
    unsigned* Aw = As[grp];
    const uint4* XD4 = (const uint4*)XDraw;

    // ---- gather: 8 nodes/warp, 4 lanes/node, lane u owns slots u, u+4, ...
    int g = lane >> 2, u = lane & 3;
    int node = gbase + 8 * half + g;
    int d = CUR[node]; if (d > ELLW) d = ELLW;
    float di = DINV[node];
    __half2 acc[4];
    {
        uint4 a0 = make_uint4(0, 0, 0, 0);
        if (u == 0) a0 = XD4[node];              // self row
        acc[0] = *(__half2*)&a0.x; acc[1] = *(__half2*)&a0.y;
        acc[2] = *(__half2*)&a0.z; acc[3] = *(__half2*)&a0.w;
    }
    const int* row = &ESRC[node * ELLW];
    {
        int s = u;
        int j = (s < d) ? row[s] : 0;
        while (s < d) {
            int sn = s + 4;
            int jn = (sn < d) ? row[sn] : 0;     // prefetch next index
            uint4 v = XD4[j];
            acc[0] = __hadd2(acc[0], *(__half2*)&v.x);
            acc[1] = __hadd2(acc[1], *(__half2*)&v.y);
            acc[2] = __hadd2(acc[2], *(__half2*)&v.z);
            acc[3] = __hadd2(acc[3], *(__half2*)&v.w);
            s = sn; j = jn;
        }
    }
    // reduce S across the 4 lanes of the group
    #pragma unroll
    for (int m = 1; m <= 2; m <<= 1) {
        #pragma unroll
        for (int p = 0; p < 4; p++) {
            unsigned av = *(unsigned*)&acc[p];
            unsigned ov = __shfl_xor_sync(0xffffffffu, av, m, 4);
            acc[p] = __hadd2(acc[p], *(__half2*)&ov);
        }
    }
    if (u == 0) {
        Ssm[w][g] = make_uint4(*(unsigned*)&acc[0], *(unsigned*)&acc[1],
                               *(unsigned*)&acc[2], *(unsigned*)&acc[3]);
        Dis[grp][8 * half + g] = di;
    }
    __syncwarp();

    // ---- A-tile build: this warp's 8 rows, A = relu(di*(S@W1) + b1)
    #pragma unroll
    for (int q = 0; q < 8; q++) {
        uint4 sv = Ssm[w][q];
        float2 f01 = __half22float2(*(__half2*)&sv.x);
        float2 f23 = __half22float2(*(__half2*)&sv.y);
        float2 f4  = __half22float2(*(__half2*)&sv.z);
        float dq = Dis[grp][8 * half + q];
        float ox = 0.f, oy = 0.f;
        float2 wv;
        wv = W1s[0 * 32 + lane]; ox += f01.x * wv.x; oy += f01.x * wv.y;
        wv = W1s[1 * 32 + lane]; ox += f01.y * wv.x; oy += f01.y * wv.y;
        wv = W1s[2 * 32 + lane]; ox += f23.x * wv.x; oy += f23.x * wv.y;
        wv = W1s[3 * 32 + lane]; ox += f23.y * wv.x; oy += f23.y * wv.y;
        wv = W1s[4 * 32 + lane]; ox += f4.x  * wv.x; oy += f4.x  * wv.y;
        float2 b = b1s[lane];
        Aw[(8 * half + q) * APITCH + lane] =
            h2pack(fmaxf(dq * ox + b.x, 0.f), fmaxf(dq * oy + b.y, 0.f));
    }
    asm volatile("bar.sync %0, 64;" :: "r"(1 + grp) : "memory");

    // ---- HMMA 16x64x64, nt split by warp half, epilogue -> HB8 (fp8)
    unsigned a0[4], a1[4], a2[4], a3[4];
    {
        int tt = lane >> 3, i = lane & 7;
        int ar = i + ((tt & 1) << 3);
        #pragma unroll
        for (int ks = 0; ks < 4; ks++) {
            unsigned addr = sm_u32(&Aw[ar * APITCH + ks * 8 + ((tt >> 1) << 2)]);
            asm volatile("ldmatrix.sync.aligned.m8n8.x4.shared.b16 {%0,%1,%2,%3}, [%4];"
                         : "=r"(a0[ks]), "=r"(a1[ks]), "=r"(a2[ks]), "=r"(a3[ks])
                         : "r"(addr));
        }
    }
    float di0 = Dis[grp][lane >> 2];
    float di1 = Dis[grp][(lane >> 2) + 8];
    int n0 = gbase + (lane >> 2);
    int n1 = n0 + 8;
    int bl = lane & 15;
    int bi = bl & 7, bh = (bl >> 3) & 1;

    int ntb = half * 4;
    #pragma unroll
    for (int q = 0; q < 4; q++) {
        int nt = ntb + q;
        float d0 = 0.f, d1 = 0.f, d2 = 0.f, d3 = 0.f;
        #pragma unroll
        for (int ks = 0; ks < 4; ks++) {
            unsigned b0, b1r;
            unsigned baddr = sm_u32(&W2h[(ks * 16 + bh * 8 + bi) * APITCH + nt * 4]);
            asm volatile("ldmatrix.sync.aligned.m8n8.x2.trans.shared.b16 {%0,%1}, [%2];"
                         : "=r"(b0), "=r"(b1r) : "r"(baddr));
            asm volatile("mma.sync.aligned.m16n8k16.row.col.f32.f16.f16.f32 "
                         "{%0,%1,%2,%3}, {%4,%5,%6,%7}, {%8,%9}, {%0,%1,%2,%3};"
                         : "+f"(d0), "+f"(d1), "+f"(d2), "+f"(d3)
                         : "r"(a0[ks]), "r"(a1[ks]), "r"(a2[ks]), "r"(a3[ks]),
                           "r"(b0), "r"(b1r));
        }
        ((unsigned short*)HB8)[n0 * 32 + nt * 4 + (lane & 3)] = e4m3pack(d1 * di0, d0 * di0);
        ((unsigned short*)HB8)[n1 * 32 + nt * 4 + (lane & 3)] = e4m3pack(d3 * di1, d2 * di1);
    }
}

// ---------------------------------------------------------------------------
__device__ __forceinline__ void fcvt_acc(unsigned wd, __half2& x, __half2& y) {
    unsigned lo, hi;
    unsigned short wl = (unsigned short)(wd & 0xffffu);
    unsigned short wh = (unsigned short)(wd >> 16);
    asm("cvt.rn.f16x2.e4m3x2 %0, %1;" : "=r"(lo) : "h"(wl));
    asm("cvt.rn.f16x2.e4m3x2 %0, %1;" : "=r"(hi) : "h"(wh));
    x = __hadd2(x, *(__half2*)&lo);
    y = __hadd2(y, *(__half2*)&hi);
}

__device__ __forceinline__ void fcvt_set(unsigned wd, __half2& x, __half2& y) {
    unsigned lo, hi;
    unsigned short wl = (unsigned short)(wd & 0xffffu);
    unsigned short wh = (unsigned short)(wd >> 16);
    asm("cvt.rn.f16x2.e4m3x2 %0, %1;" : "=r"(lo) : "h"(wl));
    asm("cvt.rn.f16x2.e4m3x2 %0, %1;" : "=r"(hi) : "h"(wh));
    x = *(__half2*)&lo;
    y = *(__half2*)&hi;
}

__device__ __forceinline__ void fold16(const uint4& v, __half2* a) {
    fcvt_acc(v.x, a[0], a[1]);
    fcvt_acc(v.y, a[2], a[3]);
    fcvt_acc(v.z, a[4], a[5]);
    fcvt_acc(v.w, a[6], a[7]);
}

// Warp gathers 8 consecutive nodes (4 lanes/node, uint4/lane = 16 fp8 feats).
__device__ __forceinline__ void gather8_to_tile(
    const uint4* __restrict__ H4,       // (NN+1) x 4 uint4, row NN zero
    const float2* __restrict__ bs2,
    int node0, int lane,
    unsigned* Arows, float* dis)
{
    int g = lane >> 2, u = lane & 3;
    int node = node0 + g;
    int d = CUR[node]; if (d > ELLW) d = ELLW;
    float di = DINV[node];
    __half2 acc[8];
    {
        uint4 v = H4[node * 4 + u];
        fcvt_set(v.x, acc[0], acc[1]);
        fcvt_set(v.y, acc[2], acc[3]);
        fcvt_set(v.z, acc[4], acc[5]);
        fcvt_set(v.w, acc[6], acc[7]);
    }
    int dmax = d;
    dmax = max(dmax, __shfl_xor_sync(0xffffffffu, dmax, 4));
    dmax = max(dmax, __shfl_xor_sync(0xffffffffu, dmax, 8));
    dmax = max(dmax, __shfl_xor_sync(0xffffffffu, dmax, 16));
    const int* row = &ESRC[node * ELLW];
    int pf = (u < d) ? row[u] : NN;
    for (int base = 0; base < dmax; base += 4) {
        int idxv = pf;
        int nb = base + 4;
        if (nb < dmax) pf = (nb + u < d) ? row[nb + u] : NN;
        int s0 = __shfl_sync(0xffffffffu, idxv, 0, 4);
        int s1 = __shfl_sync(0xffffffffu, idxv, 1, 4);
        int s2 = __shfl_sync(0xffffffffu, idxv, 2, 4);
        int s3 = __shfl_sync(0xffffffffu, idxv, 3, 4);
        uint4 n0 = H4[s0 * 4 + u];
        uint4 n1 = H4[s1 * 4 + u];
        uint4 n2 = H4[s2 * 4 + u];
        uint4 n3 = H4[s3 * 4 + u];
        fold16(n0, acc);
        fold16(n1, acc);
        fold16(n2, acc);
        fold16(n3, acc);
    }
    uint4 o0, o1;
    unsigned* po0 = (unsigned*)&o0;
    unsigned* po1 = (unsigned*)&o1;
    #pragma unroll
    for (int p = 0; p < 8; p++) {
        float2 b = bs2[u * 8 + p];
        float2 f = __half22float2(acc[p]);
        __half2 h = __floats2half2_rn(fmaxf(di * f.x + b.x, 0.f),
                                      fmaxf(di * f.y + b.y, 0.f));
        if (p < 4) po0[p] = *(unsigned*)&h; else po1[p - 4] = *(unsigned*)&h;
    }
    *(uint4*)&Arows[g * APITCH + u * 8] = o0;
    *(uint4*)&Arows[g * APITCH + u * 8 + 4] = o1;
    if (u == 0) dis[g] = di;
}

// gl3: warp-pair per 16-node group; fp8 HB8 gather; HMMA 16x16x64; -> H3 + self term.
__global__ void __launch_bounds__(512, 2) k_gl3(const float* __restrict__ W3,
                                                const float* __restrict__ b2) {
    __shared__ unsigned As[8][16 * APITCH];
    __shared__ unsigned W3h[64 * APITCH];
    __shared__ float    Dis[8][16];
    __shared__ float2   b2s[32];
    __shared__ float    sbin[16];
    int t = threadIdx.x;
    for (int idx = t; idx < 512; idx += 512) {
        int k = idx >> 3, p = idx & 7;
        __half2 wv = __floats2half2_rn(W3[k * 16 + 2 * p], W3[k * 16 + 2 * p + 1]);
        W3h[k * APITCH + p] = *(unsigned*)&wv;
    }
    if (t < 16) sbin[t] = 0.0f;
    if (t < 32) b2s[t] = ((const float2*)b2)[t];
    __syncthreads();
    int lane = t & 31, w = t >> 5;
    int grp = w >> 1, half = w & 1;
    int gw = blockIdx.x * 8 + grp;
    if (gw < NN / 16) {
        int gbase = gw * 16;
        unsigned* Aw = As[grp];
        gather8_to_tile((const uint4*)HB8, b2s, gbase + 8 * half, lane,
                        Aw + (8 * half) * APITCH, &Dis[grp][8 * half]);
        asm volatile("bar.sync %0, 64;" :: "r"(1 + grp) : "memory");

        unsigned a0[4], a1[4], a2[4], a3[4];
        {
            int tt = lane >> 3, i = lane & 7;
            int ar = i + ((tt & 1) << 3);
            #pragma unroll
            for (int ks = 0; ks < 4; ks++) {
                unsigned addr = sm_u32(&Aw[ar * APITCH + ks * 8 + ((tt >> 1) << 2)]);
                asm volatile("ldmatrix.sync.aligned.m8n8.x4.shared.b16 {%0,%1,%2,%3}, [%4];"
                             : "=r"(a0[ks]), "=r"(a1[ks]), "=r"(a2[ks]), "=r"(a3[ks])
                             : "r"(addr));
            }
        }
        float di0 = Dis[grp][lane >> 2];
        float di1 = Dis[grp][(lane >> 2) + 8];
        int n0 = gbase + (lane >> 2);
        int n1 = n0 + 8;
        int bl = lane & 15;
        int bi = bl & 7, bh = (bl >> 3) & 1;

        int nt = half;
        float d0 = 0.f, d1 = 0.f, d2 = 0.f, d3 = 0.f;
        #pragma unroll
        for (int ks = 0; ks < 4; ks++) {
            unsigned b0, b1r;
            unsigned baddr = sm_u32(&W3h[(ks * 16 + bh * 8 + bi) * APITCH + nt * 4]);
            asm volatile("ldmatrix.sync.aligned.m8n8.x2.trans.shared.b16 {%0,%1}, [%2];"
                         : "=r"(b0), "=r"(b1r) : "r"(baddr));
            asm volatile("mma.sync.aligned.m16n8k16.row.col.f32.f16.f16.f32 "
                         "{%0,%1,%2,%3}, {%4,%5,%6,%7}, {%8,%9}, {%0,%1,%2,%3};"
                         : "+f"(d0), "+f"(d1), "+f"(d2), "+f"(d3)
                         : "r"(a0[ks]), "r"(a1[ks]), "r"(a2[ks]), "r"(a3[ks]),
                           "r"(b0), "r"(b1r));
        }
        float g0 = d0 * di0, g1 = d1 * di0, g2 = d2 * di1, g3v = d3 * di1;
        H3[n0 * 8 + nt * 4 + (lane & 3)] = h2pack(g0, g1);
        H3[n1 * 8 + nt * 4 + (lane & 3)] = h2pack(g2, g3v);
        float s0 = g0 * di0 + g2 * di1;
        float s1 = g1 * di0 + g3v * di1;
        int j0 = 8 * half + 2 * (lane & 3);
        atomicAdd(&sbin[j0],     s0);
        atomicAdd(&sbin[j0 + 1], s1);
    }
    __syncthreads();
    if (t < 16) atomicAdd(&GSTATS[8 + t], sbin[t]);
}

// Edge-parallel final reduce: sum_e g3[src] * dinv[dst]. 8 lanes/edge, 4 edges/warp.
__global__ void k_gr(const int* __restrict__ ei) {
    __shared__ float sbin[16];
    int t = threadIdx.x;
    if (t < 16) sbin[t] = 0.0f;
    __syncthreads();
    int u = t & 7;
    int slot = (t >> 3) & 3;
    int gw = blockIdx.x * 8 + (t >> 5);
    int eb = gw * 64 + slot;
    float2 acc = make_float2(0.f, 0.f);
    #pragma unroll 4
    for (int it = 0; it < 16; it++) {
        int e = eb + it * 4;
        if (e < NE) {
            int src = ei[e], dst = ei[NE + e];
            unsigned v = H3[src * 8 + u];
            float2 f = __half22float2(*(__half2*)&v);
            float dd = DINV[dst];
            acc.x += f.x * dd; acc.y += f.y * dd;
        }
    }
    atomicAdd(&sbin[2 * u], acc.x);
    atomicAdd(&sbin[2 * u + 1], acc.y);
    __syncthreads();
    if (t < 16) atomicAdd(&GSTATS[8 + t], sbin[t]);
}

__device__ __forceinline__ float softplusf(float v) {
    return fmaxf(v, 0.0f) + log1pf(expf(-fabsf(v)));
}

// Final MLP head, single block of 64 threads
__global__ void k_mlp(const float* __restrict__ T, const float* __restrict__ Tm,
                      const float* __restrict__ b3,
                      const float* __restrict__ P1, const float* __restrict__ pb1,
                      const float* __restrict__ P2, const float* __restrict__ pb2,
                      const float* __restrict__ P3, const float* __restrict__ pb3,
                      float* __restrict__ out) {
    __shared__ float emb[24], h1[64], h2[32], val[4];
    int tid = threadIdx.x;
    if (tid < 16) emb[tid] = GSTATS[8 + tid] * (1.0f / NN) + b3[tid];
    if (tid == 0) {
        float ncomp = GSTATS[0], nAND = GSTATS[1], nOR = GSTATS[2];
        float slam = GSTATS[3], smu = GSTATS[4];
        float Tn = T[0] / Tm[0];
        float safe = fmaxf(ncomp, 1.0f);
        bool has = ncomp > 0.0f;
        emb[16] = ncomp; emb[17] = nAND; emb[18] = nOR; emb[19] = nAND + nOR;
        emb[20] = has ? slam / safe : 0.0f;
        emb[21] = has ? smu / safe : 0.0f;
        emb[22] = Tn * 50.0f;
        emb[23] = (1.0f / (1.0f + Tn)) * 50.0f;
    }
    __syncthreads();
    {
        float s = pb1[tid];
        #pragma unroll
        for (int k = 0; k < 24; k++) s += emb[k] * P1[k * 64 + tid];
        h1[tid] = fmaxf(s, 0.0f);
    }
    __syncthreads();
    if (tid < 32) {
        float s = pb2[tid];
        #pragma unroll
        for (int k = 0; k < 64; k++) s += h1[k] * P2[k * 32 + tid];
        h2[tid] = fmaxf(s, 0.0f);
    }
    __syncthreads();
    if (tid < 4) {
        float s = pb3[tid];
        #pragma unroll
        for (int k = 0; k < 32; k++) s += h2[k] * P3[k * 4 + tid];
        val[tid] = softplusf(s + 2.0f);
    }
    __syncthreads();
    if (tid == 0) {
        float amin = 1.0f + val[0];
        out[0] = amin;
        out[1] = amin + val[1] + 0.5f;
        float bmin = 1.0f + val[2];
        out[2] = bmin;
        out[3] = bmin + val[3] + 0.5f;
    }
    if (tid < 24) out[4 + tid] = emb[tid];
}

// ---------------------------------------------------------------------------
extern "C" void kernel_launch(void* const* d_in, const int* in_sizes, int n_in,
                              void* d_out, int out_size) {
    const float* x   = (const float*)d_in[0];
    const int*   ei  = (const int*)d_in[1];
    const float* T   = (const float*)d_in[2];
    const float* Tm  = (const float*)d_in[3];
    const float* W1  = (const float*)d_in[4];
    const float* b1  = (const float*)d_in[5];
    const float* W2  = (const float*)d_in[6];
    const float* b2  = (const float*)d_in[7];
    const float* W3  = (const float*)d_in[8];
    const float* b3  = (const float*)d_in[9];
    const float* P1  = (const float*)d_in[10];
    const float* pb1 = (const float*)d_in[11];
    const float* P2  = (const float*)d_in[12];
    const float* pb2 = (const float*)d_in[13];
    const float* P3  = (const float*)d_in[14];
    const float* pb3 = (const float*)d_in[15];
    float* out = (float*)d_out;

    void* pCUR;
    cudaGetSymbolAddress(&pCUR, CUR);
    cudaMemsetAsync(pCUR, 0, NN * sizeof(int));

    k_place<<<(NE + 255) / 256, 256>>>(ei);
    k_pre<<<(NN + 255) / 256, 256>>>(x);
    k_gl2<<<782, 512>>>(W1, b1, W2);
    k_gl3<<<782, 512>>>(W3, b2);
    k_gr<<<2344, 256>>>(ei);
    k_mlp<<<1, 64>>>(T, Tm, b3, P1, pb1, P2, pb2, P3, pb3, out);
}